// round 11
// baseline (speedup 1.0000x reference)
#include <cuda_runtime.h>
#include <cuda_bf16.h>
#include <cstdint>
#include <cmath>

// out[s,b,f,n] = sum_c Weff[s,f,c] * x[b,c,n],  Weff = sum_kl tanh(w + delta)
// Split-bf16 HMMA (hh+hl+lh, fp32 accum) -> rel_err ~5e-6.
// R11: 16 warps/SM (256thr x 2 CTA), warp tile 64x32, TK=32, 80B padded rows
// (conflict-free ldmatrix, no swizzle), cp.async double buffer.

#define F_DIM 512
#define C_DIM 256
#define B_DIM 64
#define N_DIM 4096
#define KK_DIM 9
#define MAX_S 4

#define TM 256
#define TN 64
#define TK 32
#define NCHUNK (C_DIM / TK)          // 8

#define ROWB 80                      // 32 bf16 (64B) padded to 80B
#define OFF_AH 0
#define OFF_AL (256 * ROWB)          // 20480
#define OFF_BH (2 * 256 * ROWB)      // 40960
#define OFF_BL (OFF_BH + 64 * ROWB)  // 46080
#define STAGE_B (OFF_BL + 64 * ROWB) // 51200
#define SMEM_SZ (2 * STAGE_B)        // 102400 -> 2 CTAs/SM

__device__ __nv_bfloat16 g_wh[MAX_S * F_DIM * C_DIM];
__device__ __nv_bfloat16 g_wl[MAX_S * F_DIM * C_DIM];
__device__ __nv_bfloat16 g_xh[(size_t)B_DIM * N_DIM * C_DIM];  // [b][n][c]
__device__ __nv_bfloat16 g_xl[(size_t)B_DIM * N_DIM * C_DIM];

// ---------------------------------------------------------------------------
// Kernel 1: effective weights -> bf16 hi/lo
// ---------------------------------------------------------------------------
__global__ void weff_kernel(const float* __restrict__ w,
                            const float* __restrict__ eps, int S) {
    int i = blockIdx.x * blockDim.x + threadIdx.x;
    int total = S * F_DIM * C_DIM;
    if (i >= total) return;
    int fc = i % (F_DIM * C_DIM);
    const float* wp = w + (size_t)fc * KK_DIM;
    const float* ep = eps + (size_t)i * KK_DIM;
    float acc = 0.0f;
#pragma unroll
    for (int j = 0; j < KK_DIM; j++) {
        float e = ep[j];
        acc += tanhf(wp[j] + 0.5f * logf(e / (1.0f - e)));
    }
    __nv_bfloat16 h = __float2bfloat16_rn(acc);
    g_wh[i] = h;
    g_wl[i] = __float2bfloat16_rn(acc - __bfloat162float(h));
}

// ---------------------------------------------------------------------------
// Kernel 2: x [b][c][n] f32 -> g_xh/g_xl [b][n][c] bf16 (tiled transpose)
// ---------------------------------------------------------------------------
__global__ void __launch_bounds__(256)
xsplit_kernel(const float* __restrict__ x) {
    __shared__ float tile[32][33];
    const int n0 = blockIdx.x * 32, c0 = blockIdx.y * 32, b = blockIdx.z;
    const int tx = threadIdx.x, ty = threadIdx.y;
    const float* src = x + ((size_t)b * C_DIM + c0) * N_DIM + n0;
#pragma unroll
    for (int i = 0; i < 4; i++)
        tile[ty + i * 8][tx] = src[(size_t)(ty + i * 8) * N_DIM + tx];
    __syncthreads();
    const int idx = ty * 32 + tx;
    const int cl = (idx & 15) * 2;
    const int nl = idx >> 4;
    const size_t obase = ((size_t)b * N_DIM + n0) * C_DIM + c0 + cl;
#pragma unroll
    for (int r = 0; r < 2; r++) {
        int nr = nl + r * 16;
        float f0 = tile[cl][nr], f1 = tile[cl + 1][nr];
        __nv_bfloat16 h0 = __float2bfloat16_rn(f0);
        __nv_bfloat16 h1 = __float2bfloat16_rn(f1);
        __nv_bfloat16 l0 = __float2bfloat16_rn(f0 - __bfloat162float(h0));
        __nv_bfloat16 l1 = __float2bfloat16_rn(f1 - __bfloat162float(h1));
        uint32_t hp = (uint32_t)__bfloat16_as_ushort(h0) |
                      ((uint32_t)__bfloat16_as_ushort(h1) << 16);
        uint32_t lp = (uint32_t)__bfloat16_as_ushort(l0) |
                      ((uint32_t)__bfloat16_as_ushort(l1) << 16);
        *(uint32_t*)(g_xh + obase + (size_t)nr * C_DIM) = hp;
        *(uint32_t*)(g_xl + obase + (size_t)nr * C_DIM) = lp;
    }
}

// ---------------------------------------------------------------------------
// Helpers
// ---------------------------------------------------------------------------
__device__ __forceinline__ uint32_t smem_u32(const void* p) {
    uint32_t a;
    asm("{ .reg .u64 t; cvta.to.shared.u64 t, %1; cvt.u32.u64 %0, t; }"
        : "=r"(a) : "l"(p));
    return a;
}
__device__ __forceinline__ void cpasync16(uint32_t dst, const void* src) {
    asm volatile("cp.async.cg.shared.global [%0], [%1], 16;"
                 :: "r"(dst),
                    "l"((unsigned long long)__cvta_generic_to_global(src))
                 : "memory");
}
#define CP_COMMIT() asm volatile("cp.async.commit_group;" ::: "memory")
#define CP_WAIT1()  asm volatile("cp.async.wait_group 1;" ::: "memory")
#define CP_WAIT0()  asm volatile("cp.async.wait_group 0;" ::: "memory")

#define LDM4(r, addr)                                                       \
    asm volatile("ldmatrix.sync.aligned.m8n8.x4.shared.b16 "                \
                 "{%0,%1,%2,%3}, [%4];"                                     \
                 : "=r"((r)[0]), "=r"((r)[1]), "=r"((r)[2]), "=r"((r)[3])   \
                 : "r"(addr))
#define MMA(c, a, b0, b1)                                                   \
    asm volatile("mma.sync.aligned.m16n8k16.row.col.f32.bf16.bf16.f32 "     \
                 "{%0,%1,%2,%3}, {%4,%5,%6,%7}, {%8,%9}, {%0,%1,%2,%3};"    \
                 : "+f"((c)[0]), "+f"((c)[1]), "+f"((c)[2]), "+f"((c)[3])   \
                 : "r"((a)[0]), "r"((a)[1]), "r"((a)[2]), "r"((a)[3]),      \
                   "r"(b0), "r"(b1))

// ---------------------------------------------------------------------------
// Kernel 3: GEMM. CTA 256(M=f) x 64(N=n), 8 warps (4m x 2n), warp 64x32.
// ---------------------------------------------------------------------------
__global__ void __launch_bounds__(256, 2)
gemm_mma(float* __restrict__ out) {
    extern __shared__ char smem[];
    const uint32_t sb = smem_u32(smem);
    const int tid = threadIdx.x;
    const int wid = tid >> 5, lane = tid & 31;

    const int n0 = blockIdx.x * TN;
    const int m0 = blockIdx.y * TM;
    const int bz = blockIdx.z;                  // s*64 + b
    const int s = bz >> 6, b = bz & 63;

    const __nv_bfloat16* Agh = g_wh + (size_t)s * F_DIM * C_DIM;
    const __nv_bfloat16* Agl = g_wl + (size_t)s * F_DIM * C_DIM;
    const __nv_bfloat16* Xh = g_xh + (size_t)b * N_DIM * C_DIM;
    const __nv_bfloat16* Xl = g_xl + (size_t)b * N_DIM * C_DIM;

    // warp tile bases: 4 m-warps x 2 n-warps
    const int mbw = (wid & 3) * 64, nbw = (wid >> 2) * 32;
    // ldmatrix lane geometry (R10-passed mappings)
    const int a_row = lane & 15, a_ci0 = lane >> 4;
    const int b_row = (lane & 7) + (lane >> 4) * 8, b_ci0 = (lane >> 3) & 1;

    // B loader: thread -> row r (0..63), sel picks mat + 32B half
    const int br = tid & 63;
    const int bsel = tid >> 6;                  // 0..3
    const int bmat = bsel >> 1, bpair = bsel & 1;

    float acc[4][4][4];
#pragma unroll
    for (int mt = 0; mt < 4; mt++)
#pragma unroll
        for (int j = 0; j < 4; j++)
#pragma unroll
            for (int q = 0; q < 4; q++) acc[mt][j][q] = 0.0f;

    // ---- stage loader: A 8x16B (row tid, hi+lo) + B 2x16B per thread ----
    auto load_stage = [&](int t, int buf) {
        const uint32_t base = sb + (uint32_t)buf * STAGE_B;
        const int c0 = t * TK;
        const __nv_bfloat16* ah = Agh + (size_t)(m0 + tid) * C_DIM + c0;
        const __nv_bfloat16* al = Agl + (size_t)(m0 + tid) * C_DIM + c0;
        const uint32_t ad = base + (uint32_t)tid * ROWB;
#pragma unroll
        for (int q = 0; q < 4; q++) {
            cpasync16(ad + OFF_AH + q * 16, ah + q * 8);
            cpasync16(ad + OFF_AL + q * 16, al + q * 8);
        }
        const __nv_bfloat16* bs =
            (bmat ? Xl : Xh) + (size_t)(n0 + br) * C_DIM + c0 + bpair * 16;
        const uint32_t bd = base + (bmat ? OFF_BL : OFF_BH) +
                            (uint32_t)br * ROWB + (uint32_t)bpair * 32;
        cpasync16(bd, bs);
        cpasync16(bd + 16, bs + 8);
    };

    load_stage(0, 0); CP_COMMIT();
    load_stage(1, 1); CP_COMMIT();

#pragma unroll 1
    for (int t = 0; t < NCHUNK; t++) {
        if (t < NCHUNK - 1) { CP_WAIT1(); } else { CP_WAIT0(); }
        __syncthreads();

        const uint32_t base = sb + (uint32_t)(t & 1) * STAGE_B;
#pragma unroll
        for (int k = 0; k < 2; k++) {           // two k16 steps per TK=32
            uint32_t Ah[4][4], Al[4][4], Bh[2][4], Bl[2][4];
#pragma unroll
            for (int mt = 0; mt < 4; mt++) {
                uint32_t ra = base +
                    (uint32_t)((mbw + mt * 16 + a_row) * ROWB) +
                    (uint32_t)(k * 32 + a_ci0 * 16);
                LDM4(Ah[mt], ra + OFF_AH);
                LDM4(Al[mt], ra + OFF_AL);
            }
#pragma unroll
            for (int nt = 0; nt < 2; nt++) {
                uint32_t rb = base +
                    (uint32_t)((nbw + nt * 16 + b_row) * ROWB) +
                    (uint32_t)(k * 32 + b_ci0 * 16);
                LDM4(Bh[nt], rb + OFF_BH);
                LDM4(Bl[nt], rb + OFF_BL);
            }
#pragma unroll
            for (int mt = 0; mt < 4; mt++)
#pragma unroll
                for (int j = 0; j < 4; j++) {
                    const int nt = j >> 1, i = (j & 1) * 2;
                    MMA(acc[mt][j], Ah[mt], Bh[nt][i], Bh[nt][i + 1]);
                    MMA(acc[mt][j], Ah[mt], Bl[nt][i], Bl[nt][i + 1]);
                    MMA(acc[mt][j], Al[mt], Bh[nt][i], Bh[nt][i + 1]);
                }
        }
        __syncthreads();
        if (t + 2 < NCHUNK) { load_stage(t + 2, t & 1); CP_COMMIT(); }
    }

    // ---- epilogue ----
#pragma unroll
    for (int mt = 0; mt < 4; mt++)
#pragma unroll
        for (int j = 0; j < 4; j++) {
            const int row = m0 + mbw + mt * 16 + (lane >> 2);
            const int col = n0 + nbw + j * 8 + (lane & 3) * 2;
            float* op = out + ((size_t)bz * F_DIM + row) * N_DIM + col;
            *(float2*)op = make_float2(acc[mt][j][0], acc[mt][j][1]);
            *(float2*)(op + 8 * N_DIM) =
                make_float2(acc[mt][j][2], acc[mt][j][3]);
        }
}

// ---------------------------------------------------------------------------
// Launch: inputs in metadata order: x, weight, epsilon
// ---------------------------------------------------------------------------
extern "C" void kernel_launch(void* const* d_in, const int* in_sizes, int n_in,
                              void* d_out, int out_size) {
    const float* x   = (const float*)d_in[0];
    const float* w   = (const float*)d_in[1];
    const float* eps = (const float*)d_in[2];
    float* out = (float*)d_out;

    int S = in_sizes[2] / in_sizes[1];
    if (S < 1) S = 1;
    if (S > MAX_S) S = MAX_S;

    int total = S * F_DIM * C_DIM;
    weff_kernel<<<(total + 255) / 256, 256>>>(w, eps, S);

    dim3 tgrid(N_DIM / 32, C_DIM / 32, B_DIM);
    xsplit_kernel<<<tgrid, dim3(32, 8)>>>(x);

    cudaFuncSetAttribute(gemm_mma, cudaFuncAttributeMaxDynamicSharedMemorySize,
                         SMEM_SZ);
    dim3 grid(N_DIM / TN, F_DIM / TM, S * B_DIM);
    gemm_mma<<<grid, 256, SMEM_SZ>>>(out);
}

// round 13
// speedup vs baseline: 2.9442x; 2.9442x over previous
#include <cuda_runtime.h>
#include <cuda_bf16.h>
#include <cstdint>
#include <cmath>

// out[s,b,f,n] = sum_c Weff[s,f,c] * x[b,c,n],  Weff = sum_kl tanh(w + delta)
// Split-bf16 HMMA (hh+hl+lh, fp32 accum) -> rel_err ~5e-6.
// R12: both operands pre-packed in gmem as ldmatrix-native 512B fragment
// blocks (m16k16 / n16k16, lane addr = base + lane*16): conflict-free LDSM,
// no swizzle math, contiguous stage copies. 128-thr CTAs, warp 64x32,
// launch_bounds(128,3) -> 12 warps/SM, TK=32, 3-stage cp.async ring.

#define F_DIM 512
#define C_DIM 256
#define B_DIM 64
#define N_DIM 4096
#define KK_DIM 9
#define MAX_S 4

#define TM 128
#define TN 64
#define TK 32
#define NCHUNK (C_DIM / TK)              // 8

// Stage layout (bytes): A hi 8K | A lo 8K | B hi 4K | B lo 4K
#define OFF_AH 0
#define OFF_AL 8192
#define OFF_BH 16384
#define OFF_BL 20480
#define STAGE_B 24576
#define NSTAGE 3
#define SMEM_SZ (NSTAGE * STAGE_B)       // 73728; x3 CTAs = 216KB/SM

// Pre-packed operands.
// A: [s][mblk(4)][chunk(8)] regions of 8192B = [kstep(2)][mtile(8)][512B frag]
// B: [b][nblk(64)][chunk(8)] regions of 4096B = [kstep(2)][ntile(4)][512B frag]
// A frag 512B = 4x128B sub-blocks (m0-7,k0-7)(m8-15,k0-7)(m0-7,k8-15)(m8-15,k8-15)
// B frag 512B = (n0-7,k0-7)(n0-7,k8-15)(n8-15,k0-7)(n8-15,k8-15)
// inner: row*16 + col*2   (row = m&7 or n&7, col = c&7)
__device__ __nv_bfloat16 g_wa_h[MAX_S * 4 * 8 * 4096];
__device__ __nv_bfloat16 g_wa_l[MAX_S * 4 * 8 * 4096];
__device__ __nv_bfloat16 g_xb_h[(size_t)B_DIM * 64 * 8 * 2048];
__device__ __nv_bfloat16 g_xb_l[(size_t)B_DIM * 64 * 8 * 2048];

// ---------------------------------------------------------------------------
// Kernel 1: Weff = sum tanh(w+delta) -> bf16 hi/lo, written in frag layout
// ---------------------------------------------------------------------------
__global__ void weff_kernel(const float* __restrict__ w,
                            const float* __restrict__ eps, int S) {
    int i = blockIdx.x * blockDim.x + threadIdx.x;
    int total = S * F_DIM * C_DIM;
    if (i >= total) return;
    int s = i / (F_DIM * C_DIM);
    int fc = i % (F_DIM * C_DIM);
    int f = fc / C_DIM, c = fc % C_DIM;
    const float* wp = w + (size_t)fc * KK_DIM;
    const float* ep = eps + (size_t)i * KK_DIM;
    float acc = 0.0f;
#pragma unroll
    for (int j = 0; j < KK_DIM; j++) {
        float e = ep[j];
        acc += tanhf(wp[j] + 0.5f * logf(e / (1.0f - e)));
    }
    __nv_bfloat16 h = __float2bfloat16_rn(acc);
    __nv_bfloat16 l = __float2bfloat16_rn(acc - __bfloat162float(h));
    // fragment-layout byte offset
    uint32_t region = (uint32_t)(((s * 4 + (f >> 7)) * 8 + (c >> 5)) * 8192);
    uint32_t tile = (uint32_t)(((((c >> 4) & 1) * 8) + ((f >> 4) & 7)) * 512);
    uint32_t sb = (((c >> 3) & 1) * 2 + ((f >> 3) & 1)) * 128;
    uint32_t off = region + tile + sb + (f & 7) * 16 + (c & 7) * 2;
    g_wa_h[off >> 1] = h;
    g_wa_l[off >> 1] = l;
}

// ---------------------------------------------------------------------------
// Kernel 2: x [b][c][n] f32 -> frag-packed bf16 hi/lo.
// grid(N/64, C/32, B), block 256. Tile: 32 c x 64 n via smem transpose.
// ---------------------------------------------------------------------------
__global__ void __launch_bounds__(256)
xsplit_kernel(const float* __restrict__ x) {
    __shared__ float tile[32][65];
    const int nb = blockIdx.x, ch = blockIdx.y, b = blockIdx.z;
    const int tid = threadIdx.x;
    const int tn = tid & 63, tc = tid >> 6;
    const float* src = x + ((size_t)b * C_DIM + ch * 32) * N_DIM + nb * 64;
#pragma unroll
    for (int it = 0; it < 8; it++)
        tile[tc + it * 4][tn] = src[(size_t)(tc + it * 4) * N_DIM + tn];
    __syncthreads();
    // writer: thread -> (n = tn, c-group tc*8..tc*8+7)
    const int c0 = tc * 8;
    uint32_t hp[4], lp[4];
#pragma unroll
    for (int jp = 0; jp < 4; jp++) {
        float f0 = tile[c0 + 2 * jp][tn], f1 = tile[c0 + 2 * jp + 1][tn];
        __nv_bfloat16 h0 = __float2bfloat16_rn(f0);
        __nv_bfloat16 h1 = __float2bfloat16_rn(f1);
        __nv_bfloat16 l0 = __float2bfloat16_rn(f0 - __bfloat162float(h0));
        __nv_bfloat16 l1 = __float2bfloat16_rn(f1 - __bfloat162float(h1));
        hp[jp] = (uint32_t)__bfloat16_as_ushort(h0) |
                 ((uint32_t)__bfloat16_as_ushort(h1) << 16);
        lp[jp] = (uint32_t)__bfloat16_as_ushort(l0) |
                 ((uint32_t)__bfloat16_as_ushort(l1) << 16);
    }
    const uint32_t region = (uint32_t)(((b * 64 + nb) * 8 + ch) * 4096);
    const uint32_t t512 = (uint32_t)((((tc >> 1) * 4) + (tn >> 4)) * 512);
    const uint32_t sb = (((tn >> 3) & 1) * 2 + (tc & 1)) * 128;
    const uint32_t off = region + t512 + sb + (tn & 7) * 16;   // 16B aligned
    *(uint4*)((char*)g_xb_h + off) = make_uint4(hp[0], hp[1], hp[2], hp[3]);
    *(uint4*)((char*)g_xb_l + off) = make_uint4(lp[0], lp[1], lp[2], lp[3]);
}

// ---------------------------------------------------------------------------
// Helpers
// ---------------------------------------------------------------------------
__device__ __forceinline__ uint32_t smem_u32(const void* p) {
    uint32_t a;
    asm("{ .reg .u64 t; cvta.to.shared.u64 t, %1; cvt.u32.u64 %0, t; }"
        : "=r"(a) : "l"(p));
    return a;
}
__device__ __forceinline__ void cpasync16(uint32_t dst, const void* src) {
    asm volatile("cp.async.cg.shared.global [%0], [%1], 16;"
                 :: "r"(dst),
                    "l"((unsigned long long)__cvta_generic_to_global(src))
                 : "memory");
}
#define CP_COMMIT() asm volatile("cp.async.commit_group;" ::: "memory")
#define CP_WAIT2()  asm volatile("cp.async.wait_group 2;" ::: "memory")
#define CP_WAIT1()  asm volatile("cp.async.wait_group 1;" ::: "memory")
#define CP_WAIT0()  asm volatile("cp.async.wait_group 0;" ::: "memory")

#define LDM4(r, addr)                                                       \
    asm volatile("ldmatrix.sync.aligned.m8n8.x4.shared.b16 "                \
                 "{%0,%1,%2,%3}, [%4];"                                     \
                 : "=r"((r)[0]), "=r"((r)[1]), "=r"((r)[2]), "=r"((r)[3])   \
                 : "r"(addr))
#define MMA(c, a, b0, b1)                                                   \
    asm volatile("mma.sync.aligned.m16n8k16.row.col.f32.bf16.bf16.f32 "     \
                 "{%0,%1,%2,%3}, {%4,%5,%6,%7}, {%8,%9}, {%0,%1,%2,%3};"    \
                 : "+f"((c)[0]), "+f"((c)[1]), "+f"((c)[2]), "+f"((c)[3])   \
                 : "r"((a)[0]), "r"((a)[1]), "r"((a)[2]), "r"((a)[3]),      \
                   "r"(b0), "r"(b1))

// ---------------------------------------------------------------------------
// Kernel 3: GEMM. CTA 128(M) x 64(N), 4 warps (2m x 2n), warp 64x32.
// 3-stage cp.async ring over 8 chunks of TK=32.
// ---------------------------------------------------------------------------
__global__ void __launch_bounds__(128, 3)
gemm_mma(float* __restrict__ out) {
    extern __shared__ char smem[];
    const uint32_t sbase = smem_u32(smem);
    const int tid = threadIdx.x;
    const int wid = tid >> 5, lane = tid & 31;

    const int nblk = blockIdx.x;                // n block (64 wide)
    const int mblk = blockIdx.y;                // m block (128 wide)
    const int bz = blockIdx.z;                  // s*64 + b
    const int s = bz >> 6, b = bz & 63;

    const char* gah = (const char*)g_wa_h + (size_t)((s * 4 + mblk) * 8) * 8192;
    const char* gal = (const char*)g_wa_l + (size_t)((s * 4 + mblk) * 8) * 8192;
    const char* gbh = (const char*)g_xb_h + (size_t)((b * 64 + nblk) * 8) * 4096;
    const char* gbl = (const char*)g_xb_l + (size_t)((b * 64 + nblk) * 8) * 4096;

    // warp tile bases (in 16-wide tiles)
    const int mtb = (wid & 1) * 4;              // 4 m-tiles per warp
    const int ntb = (wid >> 1) * 2;             // 2 n-tiles per warp
    const uint32_t lb = (uint32_t)lane * 16;

    float acc[4][4][4];
#pragma unroll
    for (int mt = 0; mt < 4; mt++)
#pragma unroll
        for (int j = 0; j < 4; j++)
#pragma unroll
            for (int q = 0; q < 4; q++) acc[mt][j][q] = 0.0f;

    // stage loader: 12 x 16B per thread, all contiguous copies
    auto load_stage = [&](int t, int buf) {
        const uint32_t base = sbase + (uint32_t)buf * STAGE_B;
        const uint32_t to = (uint32_t)tid * 16;
        const char* ah = gah + (size_t)t * 8192;
        const char* al = gal + (size_t)t * 8192;
        const char* bh = gbh + (size_t)t * 4096;
        const char* bl = gbl + (size_t)t * 4096;
#pragma unroll
        for (int i = 0; i < 4; i++) {
            cpasync16(base + OFF_AH + to + i * 2048, ah + to + i * 2048);
            cpasync16(base + OFF_AL + to + i * 2048, al + to + i * 2048);
        }
#pragma unroll
        for (int i = 0; i < 2; i++) {
            cpasync16(base + OFF_BH + to + i * 2048, bh + to + i * 2048);
            cpasync16(base + OFF_BL + to + i * 2048, bl + to + i * 2048);
        }
    };

    load_stage(0, 0); CP_COMMIT();
    load_stage(1, 1); CP_COMMIT();
    load_stage(2, 2); CP_COMMIT();

#pragma unroll 1
    for (int t = 0; t < NCHUNK; t++) {
        if (t <= 5) { CP_WAIT2(); }
        else if (t == 6) { CP_WAIT1(); }
        else { CP_WAIT0(); }
        __syncthreads();

        const uint32_t base = sbase + (uint32_t)(t % 3) * STAGE_B;
#pragma unroll
        for (int k = 0; k < 2; k++) {
            uint32_t Ah[4][4], Al[4][4], Bh[2][4], Bl[2][4];
#pragma unroll
            for (int mt = 0; mt < 4; mt++) {
                uint32_t ra = base + (uint32_t)((k * 8 + mtb + mt) * 512) + lb;
                LDM4(Ah[mt], ra + OFF_AH);
                LDM4(Al[mt], ra + OFF_AL);
            }
#pragma unroll
            for (int nt = 0; nt < 2; nt++) {
                uint32_t rb = base + (uint32_t)((k * 4 + ntb + nt) * 512) + lb;
                LDM4(Bh[nt], rb + OFF_BH);
                LDM4(Bl[nt], rb + OFF_BL);
            }
#pragma unroll
            for (int mt = 0; mt < 4; mt++)
#pragma unroll
                for (int j = 0; j < 4; j++) {
                    const int nt = j >> 1, i = (j & 1) * 2;
                    MMA(acc[mt][j], Ah[mt], Bh[nt][i], Bh[nt][i + 1]);
                    MMA(acc[mt][j], Ah[mt], Bl[nt][i], Bl[nt][i + 1]);
                    MMA(acc[mt][j], Al[mt], Bh[nt][i], Bh[nt][i + 1]);
                }
        }

        if (t + NSTAGE < NCHUNK) {
            __syncthreads();
            load_stage(t + NSTAGE, t % 3);
            CP_COMMIT();
        }
    }

    // ---- epilogue (R10-proven accumulator mapping) ----
    const int mbw = (wid & 1) * 64, nbw = (wid >> 1) * 32;
#pragma unroll
    for (int mt = 0; mt < 4; mt++)
#pragma unroll
        for (int j = 0; j < 4; j++) {
            const int row = mblk * TM + mbw + mt * 16 + (lane >> 2);
            const int col = nblk * TN + nbw + j * 8 + (lane & 3) * 2;
            float* op = out + ((size_t)bz * F_DIM + row) * N_DIM + col;
            *(float2*)op = make_float2(acc[mt][j][0], acc[mt][j][1]);
            *(float2*)(op + 8 * N_DIM) =
                make_float2(acc[mt][j][2], acc[mt][j][3]);
        }
}

// ---------------------------------------------------------------------------
// Launch: inputs in metadata order: x, weight, epsilon
// ---------------------------------------------------------------------------
extern "C" void kernel_launch(void* const* d_in, const int* in_sizes, int n_in,
                              void* d_out, int out_size) {
    const float* x   = (const float*)d_in[0];
    const float* w   = (const float*)d_in[1];
    const float* eps = (const float*)d_in[2];
    float* out = (float*)d_out;

    int S = in_sizes[2] / in_sizes[1];
    if (S < 1) S = 1;
    if (S > MAX_S) S = MAX_S;

    int total = S * F_DIM * C_DIM;
    weff_kernel<<<(total + 255) / 256, 256>>>(w, eps, S);

    dim3 tgrid(N_DIM / 64, C_DIM / 32, B_DIM);
    xsplit_kernel<<<tgrid, 256>>>(x);

    cudaFuncSetAttribute(gemm_mma, cudaFuncAttributeMaxDynamicSharedMemorySize,
                         SMEM_SZ);
    dim3 grid(N_DIM / TN, F_DIM / TM, S * B_DIM);
    gemm_mma<<<grid, 128, SMEM_SZ>>>(out);
}

// round 15
// speedup vs baseline: 3.8281x; 1.3002x over previous
#include <cuda_runtime.h>
#include <cuda_fp16.h>
#include <cstdint>
#include <cmath>

// out[s,b,f,n] = sum_c Weff[s,f,c] * x[b,c,n],  Weff = sum_kl tanh(w + delta)
// R14: 2-pass fp16 HMMA.  A = Weff split into fp16 hi+lo (22-bit mantissa);
// x kept as ONE fp16 operand.  out = ah*b + al*b, fp32 accum.
// Error = fp16 rounding of x (~2^-11) -> rel_err ~2.5e-4 < 1e-3.
// Operands pre-packed in gmem as ldmatrix-native 512B fragment blocks
// (lane addr = base + lane*16): conflict-free LDSM, contiguous stage copies.
// 128-thr CTAs, warp 64x32, launch_bounds(128,3) -> 12 warps/SM, TK=32,
// 3-stage cp.async ring.

#define F_DIM 512
#define C_DIM 256
#define B_DIM 64
#define N_DIM 4096
#define KK_DIM 9
#define MAX_S 4

#define TM 128
#define TN 64
#define TK 32
#define NCHUNK (C_DIM / TK)              // 8

// Stage layout (bytes): A hi 8K | A lo 8K | B 4K
#define OFF_AH 0
#define OFF_AL 8192
#define OFF_B  16384
#define STAGE_B 20480
#define NSTAGE 3
#define SMEM_SZ (NSTAGE * STAGE_B)       // 61440; x3 CTAs = 184KB/SM

// Pre-packed operands (fragment layout, see R13):
// A: [s][mblk(4)][chunk(8)] regions of 8192B = [kstep(2)][mtile(8)][512B frag]
// B: [b][nblk(64)][chunk(8)] regions of 4096B = [kstep(2)][ntile(4)][512B frag]
// A frag 512B = (m0-7,k0-7)(m8-15,k0-7)(m0-7,k8-15)(m8-15,k8-15)
// B frag 512B = (n0-7,k0-7)(n0-7,k8-15)(n8-15,k0-7)(n8-15,k8-15)
// inner: row*16 + col*2
__device__ __half g_wa_h[MAX_S * 4 * 8 * 4096];
__device__ __half g_wa_l[MAX_S * 4 * 8 * 4096];
__device__ __half g_xb[(size_t)B_DIM * 64 * 8 * 2048];

// ---------------------------------------------------------------------------
// Kernel 1: Weff = sum tanh(w+delta) -> fp16 hi/lo, written in frag layout
// ---------------------------------------------------------------------------
__global__ void weff_kernel(const float* __restrict__ w,
                            const float* __restrict__ eps, int S) {
    int i = blockIdx.x * blockDim.x + threadIdx.x;
    int total = S * F_DIM * C_DIM;
    if (i >= total) return;
    int s = i / (F_DIM * C_DIM);
    int fc = i % (F_DIM * C_DIM);
    int f = fc / C_DIM, c = fc % C_DIM;
    const float* wp = w + (size_t)fc * KK_DIM;
    const float* ep = eps + (size_t)i * KK_DIM;
    float acc = 0.0f;
#pragma unroll
    for (int j = 0; j < KK_DIM; j++) {
        float e = ep[j];
        acc += tanhf(wp[j] + 0.5f * logf(e / (1.0f - e)));
    }
    __half h = __float2half_rn(acc);
    __half l = __float2half_rn(acc - __half2float(h));
    uint32_t region = (uint32_t)(((s * 4 + (f >> 7)) * 8 + (c >> 5)) * 8192);
    uint32_t tile = (uint32_t)(((((c >> 4) & 1) * 8) + ((f >> 4) & 7)) * 512);
    uint32_t sb = (((c >> 3) & 1) * 2 + ((f >> 3) & 1)) * 128;
    uint32_t off = region + tile + sb + (f & 7) * 16 + (c & 7) * 2;
    g_wa_h[off >> 1] = h;
    g_wa_l[off >> 1] = l;
}

// ---------------------------------------------------------------------------
// Kernel 2: x [b][c][n] f32 -> frag-packed fp16 (single operand).
// grid(N/64, C/32, B), block 256. Tile: 32 c x 64 n via smem transpose.
// ---------------------------------------------------------------------------
__global__ void __launch_bounds__(256)
xsplit_kernel(const float* __restrict__ x) {
    __shared__ float tile[32][65];
    const int nb = blockIdx.x, ch = blockIdx.y, b = blockIdx.z;
    const int tid = threadIdx.x;
    const int tn = tid & 63, tc = tid >> 6;
    const float* src = x + ((size_t)b * C_DIM + ch * 32) * N_DIM + nb * 64;
#pragma unroll
    for (int it = 0; it < 8; it++)
        tile[tc + it * 4][tn] = src[(size_t)(tc + it * 4) * N_DIM + tn];
    __syncthreads();
    const int c0 = tc * 8;
    uint32_t hp[4];
#pragma unroll
    for (int jp = 0; jp < 4; jp++) {
        __half h0 = __float2half_rn(tile[c0 + 2 * jp][tn]);
        __half h1 = __float2half_rn(tile[c0 + 2 * jp + 1][tn]);
        hp[jp] = (uint32_t)__half_as_ushort(h0) |
                 ((uint32_t)__half_as_ushort(h1) << 16);
    }
    const uint32_t region = (uint32_t)(((b * 64 + nb) * 8 + ch) * 4096);
    const uint32_t t512 = (uint32_t)((((tc >> 1) * 4) + (tn >> 4)) * 512);
    const uint32_t sb = (((tn >> 3) & 1) * 2 + (tc & 1)) * 128;
    const uint32_t off = region + t512 + sb + (tn & 7) * 16;   // 16B aligned
    *(uint4*)((char*)g_xb + off) = make_uint4(hp[0], hp[1], hp[2], hp[3]);
}

// ---------------------------------------------------------------------------
// Helpers
// ---------------------------------------------------------------------------
__device__ __forceinline__ uint32_t smem_u32(const void* p) {
    uint32_t a;
    asm("{ .reg .u64 t; cvta.to.shared.u64 t, %1; cvt.u32.u64 %0, t; }"
        : "=r"(a) : "l"(p));
    return a;
}
__device__ __forceinline__ void cpasync16(uint32_t dst, const void* src) {
    asm volatile("cp.async.cg.shared.global [%0], [%1], 16;"
                 :: "r"(dst),
                    "l"((unsigned long long)__cvta_generic_to_global(src))
                 : "memory");
}
#define CP_COMMIT() asm volatile("cp.async.commit_group;" ::: "memory")
#define CP_WAIT2()  asm volatile("cp.async.wait_group 2;" ::: "memory")
#define CP_WAIT1()  asm volatile("cp.async.wait_group 1;" ::: "memory")
#define CP_WAIT0()  asm volatile("cp.async.wait_group 0;" ::: "memory")

#define LDM4(r, addr)                                                       \
    asm volatile("ldmatrix.sync.aligned.m8n8.x4.shared.b16 "                \
                 "{%0,%1,%2,%3}, [%4];"                                     \
                 : "=r"((r)[0]), "=r"((r)[1]), "=r"((r)[2]), "=r"((r)[3])   \
                 : "r"(addr))
#define MMA(c, a, b0, b1)                                                   \
    asm volatile("mma.sync.aligned.m16n8k16.row.col.f32.f16.f16.f32 "      \
                 "{%0,%1,%2,%3}, {%4,%5,%6,%7}, {%8,%9}, {%0,%1,%2,%3};"    \
                 : "+f"((c)[0]), "+f"((c)[1]), "+f"((c)[2]), "+f"((c)[3])   \
                 : "r"((a)[0]), "r"((a)[1]), "r"((a)[2]), "r"((a)[3]),      \
                   "r"(b0), "r"(b1))

// ---------------------------------------------------------------------------
// Kernel 3: GEMM. CTA 128(M) x 64(N), 4 warps (2m x 2n), warp 64x32.
// 3-stage cp.async ring over 8 chunks of TK=32; 2 fp16 passes (Ah, Al).
// ---------------------------------------------------------------------------
__global__ void __launch_bounds__(128, 3)
gemm_mma(float* __restrict__ out) {
    extern __shared__ char smem[];
    const uint32_t sbase = smem_u32(smem);
    const int tid = threadIdx.x;
    const int wid = tid >> 5, lane = tid & 31;

    const int nblk = blockIdx.x;                // n block (64 wide)
    const int mblk = blockIdx.y;                // m block (128 wide)
    const int bz = blockIdx.z;                  // s*64 + b
    const int s = bz >> 6, b = bz & 63;

    const char* gah = (const char*)g_wa_h + (size_t)((s * 4 + mblk) * 8) * 8192;
    const char* gal = (const char*)g_wa_l + (size_t)((s * 4 + mblk) * 8) * 8192;
    const char* gb  = (const char*)g_xb + (size_t)((b * 64 + nblk) * 8) * 4096;

    const int mtb = (wid & 1) * 4;              // 4 m-tiles per warp
    const int ntb = (wid >> 1) * 2;             // 2 n-tiles per warp
    const uint32_t lb = (uint32_t)lane * 16;

    float acc[4][4][4];
#pragma unroll
    for (int mt = 0; mt < 4; mt++)
#pragma unroll
        for (int j = 0; j < 4; j++)
#pragma unroll
            for (int q = 0; q < 4; q++) acc[mt][j][q] = 0.0f;

    // stage loader: 10 x 16B per thread, all contiguous copies
    auto load_stage = [&](int t, int buf) {
        const uint32_t base = sbase + (uint32_t)buf * STAGE_B;
        const uint32_t to = (uint32_t)tid * 16;
        const char* ah = gah + (size_t)t * 8192;
        const char* al = gal + (size_t)t * 8192;
        const char* bp = gb + (size_t)t * 4096;
#pragma unroll
        for (int i = 0; i < 4; i++) {
            cpasync16(base + OFF_AH + to + i * 2048, ah + to + i * 2048);
            cpasync16(base + OFF_AL + to + i * 2048, al + to + i * 2048);
        }
#pragma unroll
        for (int i = 0; i < 2; i++) {
            cpasync16(base + OFF_B + to + i * 2048, bp + to + i * 2048);
        }
    };

    load_stage(0, 0); CP_COMMIT();
    load_stage(1, 1); CP_COMMIT();
    load_stage(2, 2); CP_COMMIT();

#pragma unroll 1
    for (int t = 0; t < NCHUNK; t++) {
        if (t <= 5) { CP_WAIT2(); }
        else if (t == 6) { CP_WAIT1(); }
        else { CP_WAIT0(); }
        __syncthreads();

        const uint32_t base = sbase + (uint32_t)(t % 3) * STAGE_B;
#pragma unroll
        for (int k = 0; k < 2; k++) {
            uint32_t Ah[4][4], Al[4][4], Bf[2][4];
#pragma unroll
            for (int mt = 0; mt < 4; mt++) {
                uint32_t ra = base + (uint32_t)((k * 8 + mtb + mt) * 512) + lb;
                LDM4(Ah[mt], ra + OFF_AH);
                LDM4(Al[mt], ra + OFF_AL);
            }
#pragma unroll
            for (int nt = 0; nt < 2; nt++) {
                uint32_t rb = base + (uint32_t)((k * 4 + ntb + nt) * 512) + lb;
                LDM4(Bf[nt], rb + OFF_B);
            }
#pragma unroll
            for (int mt = 0; mt < 4; mt++)
#pragma unroll
                for (int j = 0; j < 4; j++) {
                    const int nt = j >> 1, i = (j & 1) * 2;
                    MMA(acc[mt][j], Ah[mt], Bf[nt][i], Bf[nt][i + 1]);
                    MMA(acc[mt][j], Al[mt], Bf[nt][i], Bf[nt][i + 1]);
                }
        }

        if (t + NSTAGE < NCHUNK) {
            __syncthreads();
            load_stage(t + NSTAGE, t % 3);
            CP_COMMIT();
        }
    }

    // ---- epilogue (proven accumulator mapping) ----
    const int mbw = (wid & 1) * 64, nbw = (wid >> 1) * 32;
#pragma unroll
    for (int mt = 0; mt < 4; mt++)
#pragma unroll
        for (int j = 0; j < 4; j++) {
            const int row = mblk * TM + mbw + mt * 16 + (lane >> 2);
            const int col = nblk * TN + nbw + j * 8 + (lane & 3) * 2;
            float* op = out + ((size_t)bz * F_DIM + row) * N_DIM + col;
            *(float2*)op = make_float2(acc[mt][j][0], acc[mt][j][1]);
            *(float2*)(op + 8 * N_DIM) =
                make_float2(acc[mt][j][2], acc[mt][j][3]);
        }
}

// ---------------------------------------------------------------------------
// Launch: inputs in metadata order: x, weight, epsilon
// ---------------------------------------------------------------------------
extern "C" void kernel_launch(void* const* d_in, const int* in_sizes, int n_in,
                              void* d_out, int out_size) {
    const float* x   = (const float*)d_in[0];
    const float* w   = (const float*)d_in[1];
    const float* eps = (const float*)d_in[2];
    float* out = (float*)d_out;

    int S = in_sizes[2] / in_sizes[1];
    if (S < 1) S = 1;
    if (S > MAX_S) S = MAX_S;

    int total = S * F_DIM * C_DIM;
    weff_kernel<<<(total + 255) / 256, 256>>>(w, eps, S);

    dim3 tgrid(N_DIM / 64, C_DIM / 32, B_DIM);
    xsplit_kernel<<<tgrid, 256>>>(x);

    cudaFuncSetAttribute(gemm_mma, cudaFuncAttributeMaxDynamicSharedMemorySize,
                         SMEM_SZ);
    dim3 grid(N_DIM / TN, F_DIM / TM, S * B_DIM);
    gemm_mma<<<grid, 128, SMEM_SZ>>>(out);
}

// round 17
// speedup vs baseline: 5.5402x; 1.4472x over previous
#include <cuda_runtime.h>
#include <cuda_fp16.h>
#include <cstdint>
#include <cmath>

// out[s,b,f,n] = sum_c Weff[s,f,c] * x[b,c,n],  Weff = sum_kl tanh(w + delta)
// R16: SINGLE-pass fp16 HMMA. Both operands rounded to fp16 (2^-11 each);
// measured B-only error was 2.08e-4, so total ~sqrt(2)*2.08e-4 ~ 2.9e-4 < 1e-3.
// Operands pre-packed in gmem as ldmatrix-native 512B fragment blocks
// (lane addr = base + lane*16): conflict-free LDSM, contiguous stage copies.
// 128-thr CTAs, warp 64x32, launch_bounds(128,4) -> 16 warps/SM, TK=32,
// 4-stage cp.async ring (prefetch target != active buffer -> one barrier/iter).

#define F_DIM 512
#define C_DIM 256
#define B_DIM 64
#define N_DIM 4096
#define KK_DIM 9
#define MAX_S 4

#define TM 128
#define TN 64
#define TK 32
#define NCHUNK (C_DIM / TK)              // 8

// Stage layout (bytes): A 8K | B 4K
#define OFF_A 0
#define OFF_B 8192
#define STAGE_B 12288
#define NSTAGE 4
#define SMEM_SZ (NSTAGE * STAGE_B)       // 49152; x4 CTAs = 192KB/SM

// Pre-packed operands (fragment layout, R13-proven):
// A: [s][mblk(4)][chunk(8)] regions of 8192B = [kstep(2)][mtile(8)][512B frag]
// B: [b][nblk(64)][chunk(8)] regions of 4096B = [kstep(2)][ntile(4)][512B frag]
// A frag 512B = (m0-7,k0-7)(m8-15,k0-7)(m0-7,k8-15)(m8-15,k8-15)
// B frag 512B = (n0-7,k0-7)(n0-7,k8-15)(n8-15,k0-7)(n8-15,k8-15)
// inner: row*16 + col*2
__device__ __half g_wa[MAX_S * 4 * 8 * 4096];
__device__ __half g_xb[(size_t)B_DIM * 64 * 8 * 2048];

// ---------------------------------------------------------------------------
// Kernel 1: Weff = sum tanh(w+delta) -> fp16, written in frag layout
// ---------------------------------------------------------------------------
__global__ void weff_kernel(const float* __restrict__ w,
                            const float* __restrict__ eps, int S) {
    int i = blockIdx.x * blockDim.x + threadIdx.x;
    int total = S * F_DIM * C_DIM;
    if (i >= total) return;
    int s = i / (F_DIM * C_DIM);
    int fc = i % (F_DIM * C_DIM);
    int f = fc / C_DIM, c = fc % C_DIM;
    const float* wp = w + (size_t)fc * KK_DIM;
    const float* ep = eps + (size_t)i * KK_DIM;
    float acc = 0.0f;
#pragma unroll
    for (int j = 0; j < KK_DIM; j++) {
        float e = ep[j];
        acc += tanhf(wp[j] + 0.5f * logf(e / (1.0f - e)));
    }
    uint32_t region = (uint32_t)(((s * 4 + (f >> 7)) * 8 + (c >> 5)) * 8192);
    uint32_t tile = (uint32_t)(((((c >> 4) & 1) * 8) + ((f >> 4) & 7)) * 512);
    uint32_t sb = (((c >> 3) & 1) * 2 + ((f >> 3) & 1)) * 128;
    uint32_t off = region + tile + sb + (f & 7) * 16 + (c & 7) * 2;
    g_wa[off >> 1] = __float2half_rn(acc);
}

// ---------------------------------------------------------------------------
// Kernel 2: x [b][c][n] f32 -> frag-packed fp16.
// grid(N/64, C/32, B), block 256. Tile: 32 c x 64 n via smem transpose.
// ---------------------------------------------------------------------------
__global__ void __launch_bounds__(256)
xsplit_kernel(const float* __restrict__ x) {
    __shared__ float tile[32][65];
    const int nb = blockIdx.x, ch = blockIdx.y, b = blockIdx.z;
    const int tid = threadIdx.x;
    const int tn = tid & 63, tc = tid >> 6;
    const float* src = x + ((size_t)b * C_DIM + ch * 32) * N_DIM + nb * 64;
#pragma unroll
    for (int it = 0; it < 8; it++)
        tile[tc + it * 4][tn] = src[(size_t)(tc + it * 4) * N_DIM + tn];
    __syncthreads();
    const int c0 = tc * 8;
    uint32_t hp[4];
#pragma unroll
    for (int jp = 0; jp < 4; jp++) {
        __half h0 = __float2half_rn(tile[c0 + 2 * jp][tn]);
        __half h1 = __float2half_rn(tile[c0 + 2 * jp + 1][tn]);
        hp[jp] = (uint32_t)__half_as_ushort(h0) |
                 ((uint32_t)__half_as_ushort(h1) << 16);
    }
    const uint32_t region = (uint32_t)(((b * 64 + nb) * 8 + ch) * 4096);
    const uint32_t t512 = (uint32_t)((((tc >> 1) * 4) + (tn >> 4)) * 512);
    const uint32_t sb = (((tn >> 3) & 1) * 2 + (tc & 1)) * 128;
    const uint32_t off = region + t512 + sb + (tn & 7) * 16;   // 16B aligned
    *(uint4*)((char*)g_xb + off) = make_uint4(hp[0], hp[1], hp[2], hp[3]);
}

// ---------------------------------------------------------------------------
// Helpers
// ---------------------------------------------------------------------------
__device__ __forceinline__ uint32_t smem_u32(const void* p) {
    uint32_t a;
    asm("{ .reg .u64 t; cvta.to.shared.u64 t, %1; cvt.u32.u64 %0, t; }"
        : "=r"(a) : "l"(p));
    return a;
}
__device__ __forceinline__ void cpasync16(uint32_t dst, const void* src) {
    asm volatile("cp.async.cg.shared.global [%0], [%1], 16;"
                 :: "r"(dst),
                    "l"((unsigned long long)__cvta_generic_to_global(src))
                 : "memory");
}
#define CP_COMMIT() asm volatile("cp.async.commit_group;" ::: "memory")
#define CP_WAIT2()  asm volatile("cp.async.wait_group 2;" ::: "memory")
#define CP_WAIT1()  asm volatile("cp.async.wait_group 1;" ::: "memory")
#define CP_WAIT0()  asm volatile("cp.async.wait_group 0;" ::: "memory")

#define LDM4(r, addr)                                                       \
    asm volatile("ldmatrix.sync.aligned.m8n8.x4.shared.b16 "                \
                 "{%0,%1,%2,%3}, [%4];"                                     \
                 : "=r"((r)[0]), "=r"((r)[1]), "=r"((r)[2]), "=r"((r)[3])   \
                 : "r"(addr))
#define MMA(c, a, b0, b1)                                                   \
    asm volatile("mma.sync.aligned.m16n8k16.row.col.f32.f16.f16.f32 "      \
                 "{%0,%1,%2,%3}, {%4,%5,%6,%7}, {%8,%9}, {%0,%1,%2,%3};"    \
                 : "+f"((c)[0]), "+f"((c)[1]), "+f"((c)[2]), "+f"((c)[3])   \
                 : "r"((a)[0]), "r"((a)[1]), "r"((a)[2]), "r"((a)[3]),      \
                   "r"(b0), "r"(b1))

// ---------------------------------------------------------------------------
// Kernel 3: GEMM. CTA 128(M) x 64(N), 4 warps (2m x 2n), warp 64x32.
// 4-stage cp.async ring over 8 chunks of TK=32; single fp16 pass.
// ---------------------------------------------------------------------------
__global__ void __launch_bounds__(128, 4)
gemm_mma(float* __restrict__ out) {
    extern __shared__ char smem[];
    const uint32_t sbase = smem_u32(smem);
    const int tid = threadIdx.x;
    const int wid = tid >> 5, lane = tid & 31;

    const int nblk = blockIdx.x;                // n block (64 wide)
    const int mblk = blockIdx.y;                // m block (128 wide)
    const int bz = blockIdx.z;                  // s*64 + b
    const int s = bz >> 6, b = bz & 63;

    const char* ga = (const char*)g_wa + (size_t)((s * 4 + mblk) * 8) * 8192;
    const char* gb = (const char*)g_xb + (size_t)((b * 64 + nblk) * 8) * 4096;

    const int mtb = (wid & 1) * 4;              // 4 m-tiles per warp
    const int ntb = (wid >> 1) * 2;             // 2 n-tiles per warp
    const uint32_t lb = (uint32_t)lane * 16;

    float acc[4][4][4];
#pragma unroll
    for (int mt = 0; mt < 4; mt++)
#pragma unroll
        for (int j = 0; j < 4; j++)
#pragma unroll
            for (int q = 0; q < 4; q++) acc[mt][j][q] = 0.0f;

    // stage loader: 6 x 16B per thread, all contiguous copies
    auto load_stage = [&](int t, int buf) {
        const uint32_t base = sbase + (uint32_t)buf * STAGE_B;
        const uint32_t to = (uint32_t)tid * 16;
        const char* ap = ga + (size_t)t * 8192;
        const char* bp = gb + (size_t)t * 4096;
#pragma unroll
        for (int i = 0; i < 4; i++)
            cpasync16(base + OFF_A + to + i * 2048, ap + to + i * 2048);
#pragma unroll
        for (int i = 0; i < 2; i++)
            cpasync16(base + OFF_B + to + i * 2048, bp + to + i * 2048);
    };

    load_stage(0, 0); CP_COMMIT();
    load_stage(1, 1); CP_COMMIT();
    load_stage(2, 2); CP_COMMIT();

#pragma unroll 1
    for (int t = 0; t < NCHUNK; t++) {
        if (t <= 5) { CP_WAIT2(); }
        else if (t == 6) { CP_WAIT1(); }
        else { CP_WAIT0(); }
        __syncthreads();
        // After this barrier all warps finished computing stage t-1, so its
        // buffer ((t+3)%4) is free -> prefetch stage t+3 with no second sync.
        if (t + 3 < NCHUNK) {
            load_stage(t + 3, (t + 3) & 3);
            CP_COMMIT();
        }

        const uint32_t base = sbase + (uint32_t)(t & 3) * STAGE_B;
#pragma unroll
        for (int k = 0; k < 2; k++) {
            uint32_t Af[4][4], Bf[2][4];
#pragma unroll
            for (int mt = 0; mt < 4; mt++) {
                uint32_t ra = base + (uint32_t)((k * 8 + mtb + mt) * 512) + lb;
                LDM4(Af[mt], ra + OFF_A);
            }
#pragma unroll
            for (int nt = 0; nt < 2; nt++) {
                uint32_t rb = base + (uint32_t)((k * 4 + ntb + nt) * 512) + lb;
                LDM4(Bf[nt], rb + OFF_B);
            }
#pragma unroll
            for (int mt = 0; mt < 4; mt++)
#pragma unroll
                for (int j = 0; j < 4; j++) {
                    const int nt = j >> 1, i = (j & 1) * 2;
                    MMA(acc[mt][j], Af[mt], Bf[nt][i], Bf[nt][i + 1]);
                }
        }
    }

    // ---- epilogue (proven accumulator mapping) ----
    const int mbw = (wid & 1) * 64, nbw = (wid >> 1) * 32;
#pragma unroll
    for (int mt = 0; mt < 4; mt++)
#pragma unroll
        for (int j = 0; j < 4; j++) {
            const int row = mblk * TM + mbw + mt * 16 + (lane >> 2);
            const int col = nblk * TN + nbw + j * 8 + (lane & 3) * 2;
            float* op = out + ((size_t)bz * F_DIM + row) * N_DIM + col;
            *(float2*)op = make_float2(acc[mt][j][0], acc[mt][j][1]);
            *(float2*)(op + 8 * N_DIM) =
                make_float2(acc[mt][j][2], acc[mt][j][3]);
        }
}

// ---------------------------------------------------------------------------
// Launch: inputs in metadata order: x, weight, epsilon
// ---------------------------------------------------------------------------
extern "C" void kernel_launch(void* const* d_in, const int* in_sizes, int n_in,
                              void* d_out, int out_size) {
    const float* x   = (const float*)d_in[0];
    const float* w   = (const float*)d_in[1];
    const float* eps = (const float*)d_in[2];
    float* out = (float*)d_out;

    int S = in_sizes[2] / in_sizes[1];
    if (S < 1) S = 1;
    if (S > MAX_S) S = MAX_S;

    int total = S * F_DIM * C_DIM;
    weff_kernel<<<(total + 255) / 256, 256>>>(w, eps, S);

    dim3 tgrid(N_DIM / 64, C_DIM / 32, B_DIM);
    xsplit_kernel<<<tgrid, 256>>>(x);

    cudaFuncSetAttribute(gemm_mma, cudaFuncAttributeMaxDynamicSharedMemorySize,
                         SMEM_SZ);
    dim3 grid(N_DIM / TN, F_DIM / TM, S * B_DIM);
    gemm_mma<<<grid, 128, SMEM_SZ>>>(out);
}